// round 1
// baseline (speedup 1.0000x reference)
#include <cuda_runtime.h>

// NeRF fine sampling + merge-sort kernel.
// One warp per ray. SC=64 coarse dists (sorted), 63 weights, SF=128 fine samples.
// Output per ray: 192 sorted floats (fine samples merged with coarse dists).

#define SC  64
#define SF  128
#define NOUT 192
#define WPB 8          // warps (rays) per block
#define FULLMASK 0xffffffffu

__global__ __launch_bounds__(32 * WPB, 8)
void fine_sample_kernel(const float* __restrict__ dists,
                        const float* __restrict__ weights,
                        const float* __restrict__ rands,
                        float* __restrict__ out, int B)
{
    __shared__ float cdf_s[WPB][SC];
    __shared__ float dst_s[WPB][SC];
    __shared__ float smp_s[WPB][SF];
    __shared__ float out_s[WPB][NOUT];

    const int wid  = threadIdx.x >> 5;
    const int lane = threadIdx.x & 31;
    const int ray  = blockIdx.x * WPB + wid;
    if (ray >= B) return;

    float* cdf = cdf_s[wid];
    float* dst = dst_s[wid];
    float* smp = smp_s[wid];
    float* obf = out_s[wid];

    // ---- load coarse dists (sorted) ----
    const float* dptr = dists + (size_t)ray * SC;
    float dA = dptr[lane];
    float dB = dptr[32 + lane];
    dst[lane]      = dA;
    dst[32 + lane] = dB;

    // ---- weights -> normalized CDF (64 entries, cdf[0]=0) ----
    const float* wptr = weights + (size_t)ray * (SC - 1);
    float w0 = wptr[lane] + 0.01f;                           // lanes 0..31 -> w[0..31]
    float w1 = (lane < 31) ? (wptr[32 + lane] + 0.01f) : 0.0f; // lanes 0..30 -> w[32..62]

    // inclusive warp scan of w0
    float a = w0;
    #pragma unroll
    for (int off = 1; off < 32; off <<= 1) {
        float t = __shfl_up_sync(FULLMASK, a, off);
        if (lane >= off) a += t;
    }
    float total0 = __shfl_sync(FULLMASK, a, 31);
    // inclusive warp scan of w1
    float b = w1;
    #pragma unroll
    for (int off = 1; off < 32; off <<= 1) {
        float t = __shfl_up_sync(FULLMASK, b, off);
        if (lane >= off) b += t;
    }
    float total = total0 + __shfl_sync(FULLMASK, b, 30);
    float inv = 1.0f / total;

    if (lane == 0) cdf[0] = 0.0f;
    cdf[lane + 1] = a * inv;                       // cdf[1..32]
    if (lane < 31) cdf[lane + 33] = (total0 + b) * inv; // cdf[33..63]
    __syncwarp();

    // ---- 128 inverse-CDF samples (4 per lane) ----
    const float* uptr = rands + (size_t)ray * SF;
    float r[4];
    #pragma unroll
    for (int m = 0; m < 4; m++) {
        float u = uptr[m * 32 + lane];
        // branchless searchsorted(cdf, u, side='right'):
        // find largest idx in [0,63] with cdf[idx] <= u (cdf[0]=0 <= u always).
        int idx = 0;
        #pragma unroll
        for (int step = 32; step >= 1; step >>= 1) {
            int n = idx + step;                    // n <= 63 always
            if (cdf[n] <= u) idx = n;
        }
        int below = idx;                           // = id - 1
        int above = min(SC - 1, idx + 1);          // = min(63, id)
        float c0 = cdf[below], c1 = cdf[above];
        float e0 = dst[below], e1 = dst[above];
        float den = c1 - c0;
        if (den < 1e-5f) den = 1.0f;
        float t = (u - c0) / den;
        r[m] = e0 + t * (e1 - e0);
    }

    // ---- bitonic sort of 128 values in registers (element i = m*32 + lane) ----
    #pragma unroll
    for (int k = 2; k <= SF; k <<= 1) {
        #pragma unroll
        for (int j = k >> 1; j > 0; j >>= 1) {
            if (j >= 32) {
                const int mj = j >> 5;             // 1 or 2
                #pragma unroll
                for (int m = 0; m < 4; m++) {
                    if ((m & mj) == 0) {
                        int i = m * 32 + lane;
                        bool asc = ((i & k) == 0);
                        float x = r[m], y = r[m + mj];
                        float lo = fminf(x, y), hi = fmaxf(x, y);
                        r[m]      = asc ? lo : hi;
                        r[m + mj] = asc ? hi : lo;
                    }
                }
            } else {
                #pragma unroll
                for (int m = 0; m < 4; m++) {
                    float p = __shfl_xor_sync(FULLMASK, r[m], j);
                    int i = m * 32 + lane;
                    bool asc  = ((i & k) == 0);
                    bool lowr = ((lane & j) == 0);
                    r[m] = (lowr == asc) ? fminf(r[m], p) : fmaxf(r[m], p);
                }
            }
        }
    }

    // stash sorted samples in smem for the dist-side rank search
    #pragma unroll
    for (int m = 0; m < 4; m++) smp[m * 32 + lane] = r[m];
    __syncwarp();

    // ---- merge by rank: samples go before equal dists (stable bijection) ----
    // sample at sorted rank i lands at i + #{dists < s}
    #pragma unroll
    for (int m = 0; m < 4; m++) {
        float s = r[m];
        int cnt = 0;
        #pragma unroll
        for (int step = 64; step >= 1; step >>= 1) {
            int n = cnt + step;
            if (n <= SC && dst[n - 1] < s) cnt = n;
        }
        obf[m * 32 + lane + cnt] = s;
    }
    // dist at rank j lands at j + #{samples <= d}
    #pragma unroll
    for (int q = 0; q < 2; q++) {
        int j = q * 32 + lane;
        float d = q ? dB : dA;
        int cnt = 0;
        #pragma unroll
        for (int step = 128; step >= 1; step >>= 1) {
            int n = cnt + step;
            if (n <= SF && smp[n - 1] <= d) cnt = n;
        }
        obf[j + cnt] = d;
    }
    __syncwarp();

    // ---- coalesced output ----
    float* optr = out + (size_t)ray * NOUT;
    #pragma unroll
    for (int t2 = 0; t2 < 6; t2++)
        optr[t2 * 32 + lane] = obf[t2 * 32 + lane];
}

extern "C" void kernel_launch(void* const* d_in, const int* in_sizes, int n_in,
                              void* d_out, int out_size) {
    const float* dists   = (const float*)d_in[0];
    const float* weights = (const float*)d_in[1];
    const float* rands   = (const float*)d_in[2];
    float* out = (float*)d_out;
    int B = in_sizes[0] / SC;
    int blocks = (B + WPB - 1) / WPB;
    fine_sample_kernel<<<blocks, 32 * WPB>>>(dists, weights, rands, out, B);
}

// round 2
// speedup vs baseline: 1.2663x; 1.2663x over previous
#include <cuda_runtime.h>

// NeRF fine sampling + merge. One warp per ray.
// SC=64 sorted coarse dists, 63 weights, SF=128 fine samples, out 192 sorted.
#define SC   64
#define SF   128
#define NOUT 192
#define WPB  8
#define FULL 0xffffffffu

__device__ __forceinline__ void ce(float& x, float& y, bool asc) {
    float lo = fminf(x, y), hi = fmaxf(x, y);
    x = asc ? lo : hi;
    y = asc ? hi : lo;
}

__global__ __launch_bounds__(32 * WPB, 6)
void fine_sample_kernel(const float* __restrict__ dists,
                        const float* __restrict__ weights,
                        const float* __restrict__ rands,
                        float* __restrict__ out, int B)
{
    __shared__ float2 pair_s[WPB][SC];   // (cdf[i], dist[i])
    __shared__ float  cdfs_s[WPB][SC];   // scalar cdf for search probes
    __shared__ int    hist_s[WPB][SC];   // bin histogram
    __shared__ float  out_s[WPB][NOUT];

    const int wid  = threadIdx.x >> 5;
    const int lane = threadIdx.x & 31;
    const int ray  = blockIdx.x * WPB + wid;
    if (ray >= B) return;

    float2* pair = pair_s[wid];
    float*  cdfs = cdfs_s[wid];
    int*    hist = hist_s[wid];
    float*  obf  = out_s[wid];

    // zero histogram early
    hist[lane] = 0;
    hist[lane + 32] = 0;

    // ---- load coarse dists ----
    const float* dptr = dists + (size_t)ray * SC;
    float dA = dptr[lane];
    float dB = dptr[32 + lane];

    // ---- weights -> normalized CDF ----
    const float* wptr = weights + (size_t)ray * (SC - 1);
    float w0 = wptr[lane] + 0.01f;
    float w1 = (lane < 31) ? (wptr[32 + lane] + 0.01f) : 0.0f;

    float a = w0;
    #pragma unroll
    for (int off = 1; off < 32; off <<= 1) {
        float t = __shfl_up_sync(FULL, a, off);
        if (lane >= off) a += t;
    }
    float total0 = __shfl_sync(FULL, a, 31);
    float b = w1;
    #pragma unroll
    for (int off = 1; off < 32; off <<= 1) {
        float t = __shfl_up_sync(FULL, b, off);
        if (lane >= off) b += t;
    }
    float total = total0 + __shfl_sync(FULL, b, 30);
    float inv = 1.0f / total;

    float v1 = a * inv;              // cdf[lane+1]
    float v2 = (total0 + b) * inv;   // cdf[lane+33] (valid lanes 0..30)

    if (lane == 0) cdfs[0] = 0.0f;
    cdfs[lane + 1] = v1;
    if (lane < 31) cdfs[lane + 33] = v2;

    float c32v = __shfl_sync(FULL, v1, 31);
    float cl = __shfl_up_sync(FULL, v1, 1); if (lane == 0) cl = 0.0f;
    float ch = __shfl_up_sync(FULL, v2, 1); if (lane == 0) ch = c32v;
    pair[lane]      = make_float2(cl, dA);
    pair[lane + 32] = make_float2(ch, dB);

    // register-resident top search levels
    float c16 = __shfl_sync(FULL, v1, 15);
    float c8  = __shfl_sync(FULL, v1, 7);
    float c24 = __shfl_sync(FULL, v1, 23);
    float c48 = __shfl_sync(FULL, v2, 15);
    float c40 = __shfl_sync(FULL, v2, 7);
    float c56 = __shfl_sync(FULL, v2, 23);
    __syncwarp();

    // ---- 4 samples per lane, element index i = lane*4 + m ----
    const float4* u4p = (const float4*)(rands + (size_t)ray * SF);
    float4 uu = u4p[lane];
    float uarr[4] = {uu.x, uu.y, uu.z, uu.w};
    float k[4];

    #pragma unroll
    for (int m = 0; m < 4; m++) {
        float u = uarr[m];
        int idx = (c32v <= u) ? 32 : 0;
        float p2 = idx ? c48 : c16;
        if (p2 <= u) idx += 16;
        float p3 = (idx & 32) ? ((idx & 16) ? c56 : c40)
                              : ((idx & 16) ? c24 : c8);
        if (p3 <= u) idx += 8;
        if (cdfs[idx + 4] <= u) idx += 4;
        if (cdfs[idx + 2] <= u) idx += 2;
        if (cdfs[idx + 1] <= u) idx += 1;
        int above = min(SC - 1, idx + 1);
        float2 p0 = pair[idx];
        float2 p1 = pair[above];
        float den = p1.x - p0.x;
        den = (den < 1e-5f) ? 1.0f : den;
        float t = (u - p0.x) / den;
        float s = fmaf(t, p1.y - p0.y, p0.y);
        s = fminf(s, p1.y);   // guarantees bin-monotone keys
        k[m] = __uint_as_float((__float_as_uint(s) & ~63u) | (unsigned)idx);
        atomicAdd(&hist[idx], 1);
    }
    __syncwarp();

    // ---- dist output positions from histogram prefix ----
    {
        int h0 = hist[lane], h1 = hist[lane + 32];
        int s0 = h0, s1 = h1;
        #pragma unroll
        for (int off = 1; off < 32; off <<= 1) {
            int t0 = __shfl_up_sync(FULL, s0, off);
            int t1 = __shfl_up_sync(FULL, s1, off);
            if (lane >= off) { s0 += t0; s1 += t1; }
        }
        int tot0 = __shfl_sync(FULL, s0, 31);
        int e0 = s0 - h0;            // exclusive prefix at j=lane
        int e1 = tot0 + s1 - h1;     // exclusive prefix at j=lane+32
        obf[lane + e0]      = dA;
        obf[lane + 32 + e1] = dB;
    }

    // ---- bitonic sort of 128 keys, blocked mapping i = lane*4+m ----
    ce(k[0], k[1], true);  ce(k[2], k[3], false);       // k=2
    {                                                    // k=4
        bool a4 = (lane & 1) == 0;
        ce(k[0], k[2], a4); ce(k[1], k[3], a4);
        ce(k[0], k[1], a4); ce(k[2], k[3], a4);
    }
    #pragma unroll
    for (int kk = 8; kk <= SF; kk <<= 1) {
        bool asc = (lane & (kk >> 2)) == 0;
        #pragma unroll
        for (int j = kk >> 1; j >= 4; j >>= 1) {
            int L = j >> 2;                  // lane distance
            bool domin = (((lane & L) == 0) == asc);
            #pragma unroll
            for (int m = 0; m < 4; m++) {
                float p = __shfl_xor_sync(FULL, k[m], L);
                k[m] = domin ? fminf(k[m], p) : fmaxf(k[m], p);
            }
        }
        ce(k[0], k[2], asc); ce(k[1], k[3], asc);
        ce(k[0], k[1], asc); ce(k[2], k[3], asc);
    }

    // ---- scatter samples: pos = rank + bin + 1 ----
    #pragma unroll
    for (int m = 0; m < 4; m++) {
        unsigned bits = __float_as_uint(k[m]);
        int bin = bits & 63u;
        obf[lane * 4 + m + bin + 1] = __uint_as_float(bits & ~63u);
    }
    __syncwarp();

    // ---- coalesced output ----
    float* optr = out + (size_t)ray * NOUT;
    #pragma unroll
    for (int t = 0; t < 6; t++)
        optr[t * 32 + lane] = obf[t * 32 + lane];
}

extern "C" void kernel_launch(void* const* d_in, const int* in_sizes, int n_in,
                              void* d_out, int out_size) {
    const float* dists   = (const float*)d_in[0];
    const float* weights = (const float*)d_in[1];
    const float* rands   = (const float*)d_in[2];
    float* out = (float*)d_out;
    int B = in_sizes[0] / SC;
    int blocks = (B + WPB - 1) / WPB;
    fine_sample_kernel<<<blocks, 32 * WPB>>>(dists, weights, rands, out, B);
}